// round 1
// baseline (speedup 1.0000x reference)
#include <cuda_runtime.h>
#include <stdint.h>

#define N_NODES 50000
#define F 256            // hidden == out features
#define NFEAT 1024
#define EPSV 1e-5f

// ---------------- scratch (__device__ globals; no allocation allowed) ----------------
__device__ float g_h1  [(size_t)N_NODES * F];
__device__ float g_agg1[(size_t)N_NODES * F];
__device__ float g_h2  [(size_t)N_NODES * F];
__device__ float g_agg2[(size_t)N_NODES * F];
__device__ float g_deg [N_NODES];
__device__ float g_dinv[N_NODES];
__device__ float g_bnsum[F];
__device__ float g_bnssq[F];
__device__ int   g_is64;

// ---------------- dtype detection for edge_index (int64 vs int32) ----------------
// If the buffer really is int64 (values < 50000), every odd int32 word is 0.
// If it is int32, odd words are random node ids (nonzero w.p. 1-1/50000 each).
__global__ void detect_idx_dtype(const int* ei32, int n_check) {
    __shared__ int bad;
    if (threadIdx.x == 0) bad = 0;
    __syncthreads();
    for (int i = threadIdx.x; i < n_check; i += blockDim.x)
        if (ei32[2 * i + 1] != 0) bad = 1;
    __syncthreads();
    if (threadIdx.x == 0) g_is64 = bad ? 0 : 1;
}

__device__ __forceinline__ long ld_idx(const void* ei, long i) {
    return g_is64 ? (long)((const long long*)ei)[i] : (long)((const int*)ei)[i];
}

// ---------------- degree / norm ----------------
__global__ void init_deg(int n) {
    int i = blockIdx.x * blockDim.x + threadIdx.x;
    if (i < n) g_deg[i] = 1.0f;   // self-loop weight 1
}

__global__ void edge_deg(const void* ei, const float* w, long E) {
    long e = blockIdx.x * (long)blockDim.x + threadIdx.x;
    if (e >= E) return;
    long dst = ld_idx(ei, E + e);
    atomicAdd(&g_deg[dst], w[e]);
}

__global__ void compute_dinv(int n) {
    int i = blockIdx.x * blockDim.x + threadIdx.x;
    if (i < n) {
        float d = g_deg[i];
        g_dinv[i] = d > 0.0f ? rsqrtf(fmaxf(d, 1e-30f)) : 0.0f;
    }
}

// ---------------- SGEMM: C[M,N] = (relu?)A[M,K] @ B[K,N] ----------------
// BM=128 BN=128 BK=8 TM=8 TN=8, 256 threads. N, K multiples of tile; M guarded.
template <bool RELU>
__global__ __launch_bounds__(256) void sgemm128(int M, int N, int K,
                                                const float* __restrict__ A,
                                                const float* __restrict__ B,
                                                float* __restrict__ C) {
    const int BM = 128, BN = 128, BK = 8, TM = 8, TN = 8;
    __shared__ float As[BK][BM];
    __shared__ float Bs[BK][BN];

    int tid  = threadIdx.x;
    int cRow = blockIdx.x, cCol = blockIdx.y;

    int tRow = (tid / (BN / TN)) * TM;   // 0..120
    int tCol = (tid % (BN / TN)) * TN;

    int aRow = tid / 2;                  // 0..127
    int aCol = (tid % 2) * 4;            // 0 or 4
    int bRow = tid / 32;                 // 0..7
    int bCol = (tid % 32) * 4;

    const float* Ab = A + (long)cRow * BM * K;
    const float* Bb = B + cCol * BN;

    int  gRowA  = cRow * BM + aRow;
    bool aValid = gRowA < M;

    float acc[TM][TN];
#pragma unroll
    for (int i = 0; i < TM; i++)
#pragma unroll
        for (int j = 0; j < TN; j++) acc[i][j] = 0.0f;

    for (int k0 = 0; k0 < K; k0 += BK) {
        float4 av = aValid ? *(const float4*)(Ab + (long)aRow * K + k0 + aCol)
                           : make_float4(0.f, 0.f, 0.f, 0.f);
        if (RELU) {
            av.x = fmaxf(av.x, 0.f); av.y = fmaxf(av.y, 0.f);
            av.z = fmaxf(av.z, 0.f); av.w = fmaxf(av.w, 0.f);
        }
        As[aCol + 0][aRow] = av.x;
        As[aCol + 1][aRow] = av.y;
        As[aCol + 2][aRow] = av.z;
        As[aCol + 3][aRow] = av.w;

        float4 bv = *(const float4*)(Bb + (long)(k0 + bRow) * N + bCol);
        *(float4*)&Bs[bRow][bCol] = bv;

        __syncthreads();

        float regA[TM], regB[TN];
#pragma unroll
        for (int kk = 0; kk < BK; kk++) {
#pragma unroll
            for (int i = 0; i < TM; i++) regA[i] = As[kk][tRow + i];
#pragma unroll
            for (int j = 0; j < TN; j++) regB[j] = Bs[kk][tCol + j];
#pragma unroll
            for (int i = 0; i < TM; i++)
#pragma unroll
                for (int j = 0; j < TN; j++) acc[i][j] += regA[i] * regB[j];
        }
        __syncthreads();
    }

#pragma unroll
    for (int i = 0; i < TM; i++) {
        int row = cRow * BM + tRow + i;
        if (row < M) {
            float* cp = C + (long)row * N + cCol * BN + tCol;
#pragma unroll
            for (int j = 0; j < TN; j += 4) {
                float4 v = make_float4(acc[i][j], acc[i][j + 1], acc[i][j + 2], acc[i][j + 3]);
                *(float4*)(cp + j) = v;
            }
        }
    }
}

// ---------------- aggregation ----------------
// agg[i,f] = bias[f] + dinv[i]^2 * h[i,f]   (self-loop contribution + bias)
__global__ void agg_init(const float* __restrict__ h, const float* __restrict__ bias,
                         float* __restrict__ agg, int M) {
    long i = blockIdx.x * (long)blockDim.x + threadIdx.x;
    if (i >= (long)M * F) return;
    long r = i >> 8;
    int  f = (int)(i & 255);
    float di = g_dinv[r];
    agg[i] = bias[f] + di * di * h[i];
}

// one warp per edge: agg[dst,:] += dinv[src]*w*dinv[dst] * h[src,:]
__global__ void edge_agg(const void* __restrict__ ei, const float* __restrict__ w,
                         const float* __restrict__ h, float* __restrict__ agg, long E) {
    long warp = (blockIdx.x * (long)blockDim.x + threadIdx.x) >> 5;
    int  lane = threadIdx.x & 31;
    if (warp >= E) return;
    long src = ld_idx(ei, warp);
    long dst = ld_idx(ei, E + warp);
    float nw = g_dinv[src] * w[warp] * g_dinv[dst];
    const float* hs = h + src * F;
    float* ad = agg + dst * F;
#pragma unroll
    for (int f = lane; f < F; f += 32)
        atomicAdd(ad + f, nw * hs[f]);
}

// ---------------- batchnorm stats over relu(agg2) ----------------
__global__ void bn_zero() {
    int f = threadIdx.x;
    g_bnsum[f] = 0.0f;
    g_bnssq[f] = 0.0f;
}

__global__ void bn_stats(const float* __restrict__ agg2, int M, int rows_per_block) {
    int f = threadIdx.x;                 // 256 threads: one per feature
    long r0 = blockIdx.x * (long)rows_per_block;
    long r1 = r0 + rows_per_block; if (r1 > M) r1 = M;
    float s = 0.f, ss = 0.f;
    for (long r = r0; r < r1; r++) {
        float v = fmaxf(agg2[r * F + f], 0.f);
        s += v; ss += v * v;
    }
    atomicAdd(&g_bnsum[f], s);
    atomicAdd(&g_bnssq[f], ss);
}

// ---------------- fused relu + BN + LN epilogue ----------------
__global__ void bn_ln_final(const float* __restrict__ agg2,
                            const float* __restrict__ bg, const float* __restrict__ bb,
                            const float* __restrict__ lg, const float* __restrict__ lb,
                            float* __restrict__ out, int M) {
    long r = blockIdx.x;
    int  f = threadIdx.x;
    int  lane = f & 31, wid = f >> 5;
    float invM = 1.0f / (float)M;

    float mu  = g_bnsum[f] * invM;
    float var = g_bnssq[f] * invM - mu * mu;
    float v = fmaxf(agg2[r * F + f], 0.f);
    float y = (v - mu) * rsqrtf(var + EPSV) * bg[f] + bb[f];

    // LN over 256 features: reduce sum and sumsq
    float s = y, ss = y * y;
#pragma unroll
    for (int o = 16; o > 0; o >>= 1) {
        s  += __shfl_xor_sync(0xffffffffu, s,  o);
        ss += __shfl_xor_sync(0xffffffffu, ss, o);
    }
    __shared__ float reds[8], redss[8];
    if (lane == 0) { reds[wid] = s; redss[wid] = ss; }
    __syncthreads();
    if (wid == 0) {
        float a = lane < 8 ? reds[lane]  : 0.f;
        float b = lane < 8 ? redss[lane] : 0.f;
#pragma unroll
        for (int o = 4; o > 0; o >>= 1) {
            a += __shfl_xor_sync(0xffffffffu, a, o);
            b += __shfl_xor_sync(0xffffffffu, b, o);
        }
        if (lane == 0) { reds[0] = a; redss[0] = b; }
    }
    __syncthreads();
    float lmu  = reds[0]  * (1.0f / F);
    float lvar = redss[0] * (1.0f / F) - lmu * lmu;
    out[r * F + f] = (y - lmu) * rsqrtf(lvar + EPSV) * lg[f] + lb[f];
}

// ---------------- launcher ----------------
extern "C" void kernel_launch(void* const* d_in, const int* in_sizes, int n_in,
                              void* d_out, int out_size) {
    const float* x  = (const float*)d_in[0];
    const void*  ei = d_in[1];
    const float* ew = (const float*)d_in[2];
    const float* W1 = (const float*)d_in[3];
    const float* b1 = (const float*)d_in[4];
    const float* W2 = (const float*)d_in[5];
    const float* b2 = (const float*)d_in[6];
    const float* bg = (const float*)d_in[7];
    const float* bb = (const float*)d_in[8];
    const float* lg = (const float*)d_in[9];
    const float* lb = (const float*)d_in[10];
    float* out = (float*)d_out;

    int  n = in_sizes[0] / NFEAT;            // 50000
    long E = in_sizes[1] / 2;                // 800000 (element count same for i32/i64)

    float* h1;   cudaGetSymbolAddress((void**)&h1,   g_h1);
    float* agg1; cudaGetSymbolAddress((void**)&agg1, g_agg1);
    float* h2;   cudaGetSymbolAddress((void**)&h2,   g_h2);
    float* agg2; cudaGetSymbolAddress((void**)&agg2, g_agg2);

    // 0) edge_index dtype detection
    detect_idx_dtype<<<1, 256>>>((const int*)ei, 1024);

    // 1) degree + norm
    init_deg<<<(n + 255) / 256, 256>>>(n);
    edge_deg<<<(int)((E + 255) / 256), 256>>>(ei, ew, E);
    compute_dinv<<<(n + 255) / 256, 256>>>(n);

    long nf = (long)n * F;
    int  blkNF = (int)((nf + 255) / 256);
    int  edgeBlocks = (int)((E + 7) / 8);    // 8 warps/block, 1 warp/edge

    // 2) layer 1: h1 = x @ W1 ; agg1 = b1 + norm-weighted sum
    sgemm128<false><<<dim3((n + 127) / 128, F / 128), 256>>>(n, F, NFEAT, x, W1, h1);
    agg_init<<<blkNF, 256>>>(h1, b1, agg1, n);
    edge_agg<<<edgeBlocks, 256>>>(ei, ew, h1, agg1, E);

    // 3) layer 2: h2 = relu(agg1) @ W2 ; agg2 = b2 + norm-weighted sum
    sgemm128<true><<<dim3((n + 127) / 128, F / 128), 256>>>(n, F, F, agg1, W2, h2);
    agg_init<<<blkNF, 256>>>(h2, b2, agg2, n);
    edge_agg<<<edgeBlocks, 256>>>(ei, ew, h2, agg2, E);

    // 4) BN stats over relu(agg2)
    bn_zero<<<1, F>>>();
    const int RPB = 128;
    bn_stats<<<(n + RPB - 1) / RPB, F>>>(agg2, n, RPB);

    // 5) fused relu + BN + LN
    bn_ln_final<<<n, F>>>(agg2, bg, bb, lg, lb, out, n);
}